// round 1
// baseline (speedup 1.0000x reference)
#include <cuda_runtime.h>
#include <cuda_bf16.h>
#include <math.h>

#define NN 50000
#define NE 800000
#define NT 17

// ---------------- scratch (device globals; no allocation allowed) ------------
__device__ float    g_nf0[NN * 64];
__device__ float    g_nf1[NN * 64];
__device__ float    g_ef0[NE * 64];
__device__ float    g_ef1[NE * 64];
__device__ float    g_hsrc[NN * 128];
__device__ float    g_htgt[NN * 128];
__device__ float    g_aggr[NN * 64];
__device__ unsigned g_segmax[NN * NT];
__device__ float    g_segsum[NN * NT];
__device__ float    g_ex[NE];     // scores, then exp(score-max)
__device__ float    g_sig[NE];    // sigmoid(edge_pred)
__device__ int      g_seg[NE];
__device__ float    g_emb[NN * 64];
__device__ int      g_ntype[NN];

// ordered-uint encoding for float atomicMax
__device__ __forceinline__ unsigned fkey(float f) {
    unsigned u = __float_as_uint(f);
    return (u & 0x80000000u) ? ~u : (u | 0x80000000u);
}
__device__ __forceinline__ float funkey(unsigned u) {
    return __uint_as_float((u & 0x80000000u) ? (u & 0x7fffffffu) : ~u);
}

// ---------------- fused 2-layer MLP, dims 64 -> 64 -> 64 ---------------------
// Y = relu(X@W1 + b1)@W2 + b2.  256 threads: 4 groups x 64 cols, 16 rows/tile.
__global__ void __launch_bounds__(256) mlp2_646464(
    const float* __restrict__ X, float* __restrict__ Y,
    const float* __restrict__ W1, const float* __restrict__ B1,
    const float* __restrict__ W2, const float* __restrict__ B2, int M)
{
    __shared__ float sW1t[64 * 68];
    __shared__ float sW2t[64 * 68];
    __shared__ float sB1[64], sB2[64];
    __shared__ float sX[16 * 68];
    __shared__ float sH[16 * 68];
    int t = threadIdx.x;
    for (int idx = t; idx < 4096; idx += 256) {
        int k = idx >> 6, j = idx & 63;
        sW1t[j * 68 + k] = W1[idx];
        sW2t[j * 68 + k] = W2[idx];
    }
    if (t < 64) { sB1[t] = B1[t]; sB2[t] = B2[t]; }
    __syncthreads();
    int j = t & 63, g = t >> 6;
    int ntiles = M >> 4;
    for (int tile = blockIdx.x; tile < ntiles; tile += gridDim.x) {
        int row0 = tile << 4;
        for (int idx = t; idx < 1024; idx += 256) {
            int r = idx >> 6, k = idx & 63;
            sX[r * 68 + k] = X[(row0 + r) * 64 + k];
        }
        __syncthreads();
        float acc[4];
#pragma unroll
        for (int r = 0; r < 4; r++) acc[r] = sB1[j];
        const float4* w4 = (const float4*)(sW1t + j * 68);
#pragma unroll
        for (int kk = 0; kk < 16; kk++) {
            float4 w = w4[kk];
#pragma unroll
            for (int r = 0; r < 4; r++) {
                float4 xv = ((const float4*)(sX + (g * 4 + r) * 68))[kk];
                acc[r] += w.x * xv.x + w.y * xv.y + w.z * xv.z + w.w * xv.w;
            }
        }
#pragma unroll
        for (int r = 0; r < 4; r++)
            sH[(g * 4 + r) * 68 + j] = fmaxf(acc[r], 0.f);
        __syncthreads();
#pragma unroll
        for (int r = 0; r < 4; r++) acc[r] = sB2[j];
        const float4* w24 = (const float4*)(sW2t + j * 68);
#pragma unroll
        for (int kk = 0; kk < 16; kk++) {
            float4 w = w24[kk];
#pragma unroll
            for (int r = 0; r < 4; r++) {
                float4 hv = ((const float4*)(sH + (g * 4 + r) * 68))[kk];
                acc[r] += w.x * hv.x + w.y * hv.y + w.z * hv.z + w.w * hv.w;
            }
        }
#pragma unroll
        for (int r = 0; r < 4; r++)
            Y[(row0 + g * 4 + r) * 64 + j] = acc[r];
        __syncthreads();
    }
}

// ---------------- per-node partials: hsrc = nf@W1[0:64], htgt = nf@W1[64:128]
__global__ void __launch_bounds__(128) node_partials(
    const float* __restrict__ nf, const float* __restrict__ W1,
    float* __restrict__ hsrc, float* __restrict__ htgt, int M)
{
    __shared__ float sX[4 * 68];
    int t = threadIdx.x; // hidden col 0..127
    int ntiles = M >> 2;
    for (int tile = blockIdx.x; tile < ntiles; tile += gridDim.x) {
        int row0 = tile << 2;
        for (int idx = t; idx < 256; idx += 128) {
            int r = idx >> 6, k = idx & 63;
            sX[r * 68 + k] = nf[(row0 + r) * 64 + k];
        }
        __syncthreads();
        float accs[4] = {0, 0, 0, 0}, acct[4] = {0, 0, 0, 0};
        for (int k = 0; k < 64; k++) {
            float ws = W1[k * 128 + t];
            float wt = W1[(64 + k) * 128 + t];
#pragma unroll
            for (int r = 0; r < 4; r++) {
                float xv = sX[r * 68 + k];
                accs[r] += xv * ws;
                acct[r] += xv * wt;
            }
        }
#pragma unroll
        for (int r = 0; r < 4; r++) {
            hsrc[(row0 + r) * 128 + t] = accs[r];
            htgt[(row0 + r) * 128 + t] = acct[r];
        }
        __syncthreads();
    }
}

// ---------------- edge message: h=relu(ef@W1e + hsrc[s] + htgt[t] + b1),
//                  m = h@W2 + b2; write m; atomicAdd aggr[tgt] -----------------
extern __shared__ float dsm[];
__global__ void __launch_bounds__(128) edge_msg(
    const float* __restrict__ ef, const int* __restrict__ src, const int* __restrict__ tgt,
    const float* __restrict__ hsrc, const float* __restrict__ htgt,
    const float* __restrict__ W1, const float* __restrict__ B1,
    const float* __restrict__ W2, const float* __restrict__ B2,
    float* __restrict__ m_out, float* __restrict__ aggr)
{
    float* sW1t = dsm;                 // [128][68]
    float* sW2t = dsm + 8704;          // [64][132]
    float* sB1  = dsm + 8704 + 8448;   // 128
    float* sB2  = sB1 + 128;           // 64
    float* sEf  = sB2 + 64;            // [8][68]
    float* sH   = sEf + 544;           // [8][132]
    int*   sIdx = (int*)(sH + 1056);   // src[8], tgt[8]
    int t = threadIdx.x;
    for (int idx = t; idx < 64 * 128; idx += 128) {
        int k = idx >> 7, j = idx & 127;
        sW1t[j * 68 + k] = W1[(128 + k) * 128 + j];
    }
    for (int idx = t; idx < 128 * 64; idx += 128) {
        int k = idx >> 6, j = idx & 63;
        sW2t[j * 132 + k] = W2[idx];
    }
    sB1[t] = B1[t];
    if (t < 64) sB2[t] = B2[t];
    __syncthreads();
    int jj = t & 63, g = t >> 6;
    for (int tile = blockIdx.x; tile < NE / 8; tile += gridDim.x) {
        int e0 = tile * 8;
        if (t < 16) {
            int e = t & 7;
            sIdx[t] = (t < 8) ? src[e0 + e] : tgt[e0 + e];
        }
        for (int idx = t; idx < 512; idx += 128) {
            int r = idx >> 6, k = idx & 63;
            sEf[r * 68 + k] = ef[(e0 + r) * 64 + k];
        }
        __syncthreads();
        // phase 1: thread t computes hidden col t for 8 edges
        float acc[8];
#pragma unroll
        for (int e = 0; e < 8; e++)
            acc[e] = sB1[t] + hsrc[sIdx[e] * 128 + t] + htgt[sIdx[8 + e] * 128 + t];
        const float4* w4 = (const float4*)(sW1t + t * 68);
#pragma unroll
        for (int kk = 0; kk < 16; kk++) {
            float4 w = w4[kk];
#pragma unroll
            for (int e = 0; e < 8; e++) {
                float4 xv = ((const float4*)(sEf + e * 68))[kk];
                acc[e] += w.x * xv.x + w.y * xv.y + w.z * xv.z + w.w * xv.w;
            }
        }
#pragma unroll
        for (int e = 0; e < 8; e++)
            sH[e * 132 + t] = fmaxf(acc[e], 0.f);
        __syncthreads();
        // phase 2: thread (g, jj) computes out col jj for edges {g, g+2, g+4, g+6}
        float acc2[4];
#pragma unroll
        for (int r = 0; r < 4; r++) acc2[r] = sB2[jj];
        const float4* w24 = (const float4*)(sW2t + jj * 132);
#pragma unroll
        for (int kk = 0; kk < 32; kk++) {
            float4 w = w24[kk];
#pragma unroll
            for (int r = 0; r < 4; r++) {
                float4 hv = ((const float4*)(sH + (2 * r + g) * 132))[kk];
                acc2[r] += w.x * hv.x + w.y * hv.y + w.z * hv.z + w.w * hv.w;
            }
        }
#pragma unroll
        for (int r = 0; r < 4; r++) {
            int e = 2 * r + g;
            float v = acc2[r];
            m_out[(e0 + e) * 64 + jj] = v;
            atomicAdd(&aggr[sIdx[8 + e] * 64 + jj], v);
        }
        __syncthreads();
    }
}

// ---------------- node update: nf' = [nf, aggr] @ nu_w1 + b ------------------
__global__ void __launch_bounds__(128) node_update(
    const float* __restrict__ nf, const float* __restrict__ aggr,
    const float* __restrict__ W, const float* __restrict__ B,
    float* __restrict__ out, int M)
{
    __shared__ float sX[8 * 68];
    __shared__ float sA[8 * 68];
    int t = threadIdx.x;
    int j = t & 63, g = t >> 6;
    int ntiles = M >> 3;
    for (int tile = blockIdx.x; tile < ntiles; tile += gridDim.x) {
        int row0 = tile << 3;
        for (int idx = t; idx < 512; idx += 128) {
            int r = idx >> 6, k = idx & 63;
            sX[r * 68 + k] = nf[(row0 + r) * 64 + k];
            sA[r * 68 + k] = aggr[(row0 + r) * 64 + k];
        }
        __syncthreads();
        float acc[4];
#pragma unroll
        for (int r = 0; r < 4; r++) acc[r] = B[j];
        for (int k = 0; k < 64; k++) {
            float w1 = W[k * 64 + j];
            float w2 = W[(64 + k) * 64 + j];
#pragma unroll
            for (int r = 0; r < 4; r++) {
                int rr = g * 4 + r;
                acc[r] += sX[rr * 68 + k] * w1 + sA[rr * 68 + k] * w2;
            }
        }
#pragma unroll
        for (int r = 0; r < 4; r++)
            out[(row0 + g * 4 + r) * 64 + j] = acc[r];
        __syncthreads();
    }
}

// ---------------- node heads: node_pred, class_pred(+argmax), emb ------------
__global__ void __launch_bounds__(64) node_heads(
    const float* __restrict__ nf,
    const float* __restrict__ nc_w1, const float* __restrict__ nc_b1,
    const float* __restrict__ nc_w2, const float* __restrict__ nc_b2,
    const float* __restrict__ cl_w1, const float* __restrict__ cl_b1,
    const float* __restrict__ cl_w2, const float* __restrict__ cl_b2,
    const float* __restrict__ ce_w, const float* __restrict__ ce_b,
    float* __restrict__ node_pred, float* __restrict__ class_pred,
    int* __restrict__ ntype, float* __restrict__ emb, int M)
{
    __shared__ float sX[64];
    __shared__ float sHn[64];
    __shared__ float sHc[64];
    __shared__ float sRed[2];
    __shared__ float sCls[17];
    int t = threadIdx.x;
    for (int n = blockIdx.x; n < M; n += gridDim.x) {
        sX[t] = nf[n * 64 + t];
        __syncthreads();
        float an = nc_b1[t], ac = cl_b1[t], ae = ce_b[t];
        for (int k = 0; k < 64; k++) {
            float xv = sX[k];
            an += xv * nc_w1[k * 64 + t];
            ac += xv * cl_w1[k * 64 + t];
            ae += xv * ce_w[k * 64 + t];
        }
        sHn[t] = fmaxf(an, 0.f);
        sHc[t] = fmaxf(ac, 0.f);
        emb[n * 64 + t] = ae;
        __syncthreads();
        float p = sHn[t] * nc_w2[t];
#pragma unroll
        for (int o = 16; o > 0; o >>= 1) p += __shfl_down_sync(0xffffffffu, p, o);
        if ((t & 31) == 0) sRed[t >> 5] = p;
        __syncthreads();
        if (t == 0) node_pred[n] = sRed[0] + sRed[1] + nc_b2[0];
        if (t < 17) {
            float c = cl_b2[t];
            for (int k = 0; k < 64; k++) c += sHc[k] * cl_w2[k * 17 + t];
            class_pred[n * 17 + t] = c;
            sCls[t] = c;
        }
        __syncthreads();
        if (t == 0) {
            int best = 0; float bv = sCls[0];
#pragma unroll
            for (int c = 1; c < 17; c++)
                if (sCls[c] > bv) { bv = sCls[c]; best = c; }
            ntype[n] = best;
        }
        __syncthreads();
    }
}

// ---------------- edge head: sigmoid(edge_pred), scores, seg, segment max ----
__global__ void __launch_bounds__(128) edge_head(
    const float* __restrict__ ef, const int* __restrict__ src, const int* __restrict__ tgt,
    const float* __restrict__ W1, const float* __restrict__ B1,
    const float* __restrict__ W2v, const float* __restrict__ B2,
    const float* __restrict__ emb, const int* __restrict__ ntype,
    float* __restrict__ sig_out, float* __restrict__ score_out, int* __restrict__ seg_out,
    unsigned* __restrict__ segmax)
{
    __shared__ float sW1t[64 * 68];
    __shared__ float sW2[64];
    __shared__ float sEf[8 * 68];
    __shared__ float sRed[4][4];
    __shared__ float sRedS[4][4];
    __shared__ int sSrc[8], sTgt[8];
    int t = threadIdx.x;
    for (int idx = t; idx < 4096; idx += 128) {
        int k = idx >> 6, j = idx & 63;
        sW1t[j * 68 + k] = W1[idx];
    }
    if (t < 64) sW2[t] = W2v[t];
    __syncthreads();
    int j = t & 63, g = t >> 6, w = t >> 5, lane = t & 31;
    for (int tile = blockIdx.x; tile < NE / 8; tile += gridDim.x) {
        int e0 = tile * 8;
        if (t < 8) { sSrc[t] = src[e0 + t]; sTgt[t] = tgt[e0 + t]; }
        for (int idx = t; idx < 512; idx += 128) {
            int r = idx >> 6, k = idx & 63;
            sEf[r * 68 + k] = ef[(e0 + r) * 64 + k];
        }
        __syncthreads();
        float acc[4];
#pragma unroll
        for (int r = 0; r < 4; r++) acc[r] = B1[j];
        const float4* w4 = (const float4*)(sW1t + j * 68);
#pragma unroll
        for (int kk = 0; kk < 16; kk++) {
            float4 wv = w4[kk];
#pragma unroll
            for (int r = 0; r < 4; r++) {
                float4 xv = ((const float4*)(sEf + (g * 4 + r) * 68))[kk];
                acc[r] += wv.x * xv.x + wv.y * xv.y + wv.z * xv.z + wv.w * xv.w;
            }
        }
        float w2j = sW2[j];
        float sc[4];
#pragma unroll
        for (int r = 0; r < 4; r++) {
            int e = g * 4 + r;
            acc[r] = fmaxf(acc[r], 0.f) * w2j;
            sc[r] = emb[sSrc[e] * 64 + j] * emb[sTgt[e] * 64 + j];
        }
#pragma unroll
        for (int r = 0; r < 4; r++) {
            float p = acc[r], s = sc[r];
#pragma unroll
            for (int o = 16; o > 0; o >>= 1) {
                p += __shfl_down_sync(0xffffffffu, p, o);
                s += __shfl_down_sync(0xffffffffu, s, o);
            }
            if (lane == 0) { sRed[w][r] = p; sRedS[w][r] = s; }
        }
        __syncthreads();
        if (t < 8) {
            int gg = t >> 2, r = t & 3;
            int e = gg * 4 + r;
            float pred = sRed[2 * gg][r] + sRed[2 * gg + 1][r] + B2[0];
            float score = sRedS[2 * gg][r] + sRedS[2 * gg + 1][r];
            sig_out[e0 + e] = 1.f / (1.f + expf(-pred));
            score_out[e0 + e] = score;
            int sgv = sTgt[e] * NT + ntype[sSrc[e]];
            seg_out[e0 + e] = sgv;
            atomicMax(&segmax[sgv], fkey(score));
        }
        __syncthreads();
    }
}

__global__ void softmax_pass2(const int* __restrict__ seg, const unsigned* __restrict__ segmax,
                              float* __restrict__ score_ex, float* __restrict__ segsum)
{
    int e = blockIdx.x * blockDim.x + threadIdx.x;
    if (e >= NE) return;
    int s = seg[e];
    float ex = expf(score_ex[e] - funkey(segmax[s]));
    score_ex[e] = ex;
    atomicAdd(&segsum[s], ex);
}

__global__ void softmax_pass3(const int* __restrict__ seg, const float* __restrict__ segsum,
                              const float* __restrict__ ex, const float* __restrict__ sig,
                              float* __restrict__ out_edge)
{
    int e = blockIdx.x * blockDim.x + threadIdx.x;
    if (e >= NE) return;
    out_edge[e] = ex[e] / segsum[seg[e]] * sig[e];
}

// ---------------------------------------------------------------------------
extern "C" void kernel_launch(void* const* d_in, const int* in_sizes, int n_in,
                              void* d_out, int out_size)
{
    (void)in_sizes; (void)n_in; (void)out_size;
    const float* x     = (const float*)d_in[0];
    const float* eattr = (const float*)d_in[1];
    const int*   ei    = (const int*)d_in[2];
    // d_in[3] = node_types (unused by reference)
    const float *ne_w1 = (const float*)d_in[4],  *ne_b1 = (const float*)d_in[5];
    const float *ne_w2 = (const float*)d_in[6],  *ne_b2 = (const float*)d_in[7];
    const float *ee_w1 = (const float*)d_in[8],  *ee_b1 = (const float*)d_in[9];
    const float *ee_w2 = (const float*)d_in[10], *ee_b2 = (const float*)d_in[11];
    const float *me_w1 = (const float*)d_in[12], *me_b1 = (const float*)d_in[13];
    const float *me_w2 = (const float*)d_in[14], *me_b2 = (const float*)d_in[15];
    const float *nu_w1 = (const float*)d_in[16], *nu_b1 = (const float*)d_in[17];
    const float *ec_w1 = (const float*)d_in[18], *ec_b1 = (const float*)d_in[19];
    const float *ec_w2 = (const float*)d_in[20], *ec_b2 = (const float*)d_in[21];
    const float *nc_w1 = (const float*)d_in[22], *nc_b1 = (const float*)d_in[23];
    const float *nc_w2 = (const float*)d_in[24], *nc_b2 = (const float*)d_in[25];
    const float *cl_w1 = (const float*)d_in[26], *cl_b1 = (const float*)d_in[27];
    const float *cl_w2 = (const float*)d_in[28], *cl_b2 = (const float*)d_in[29];
    const float *ce_w  = (const float*)d_in[30], *ce_b  = (const float*)d_in[31];

    const int* src = ei;
    const int* tgt = ei + NE;

    float* out       = (float*)d_out;
    float* out_edge  = out;                     // [E]
    float* out_node  = out_edge + NE;           // [N]
    float* out_class = out_node + NN;           // [N,17]
    float* out_nf    = out_class + NN * NT;     // [N,64]
    float* out_ef    = out_nf + NN * 64;        // [E,64]

    float *nf0, *nf1, *ef0, *ef1, *hsrc, *htgt, *aggr, *segsum, *ex, *sig, *emb;
    unsigned* segmax; int *seg, *ntype;
    cudaGetSymbolAddress((void**)&nf0,    g_nf0);
    cudaGetSymbolAddress((void**)&nf1,    g_nf1);
    cudaGetSymbolAddress((void**)&ef0,    g_ef0);
    cudaGetSymbolAddress((void**)&ef1,    g_ef1);
    cudaGetSymbolAddress((void**)&hsrc,   g_hsrc);
    cudaGetSymbolAddress((void**)&htgt,   g_htgt);
    cudaGetSymbolAddress((void**)&aggr,   g_aggr);
    cudaGetSymbolAddress((void**)&segmax, g_segmax);
    cudaGetSymbolAddress((void**)&segsum, g_segsum);
    cudaGetSymbolAddress((void**)&ex,     g_ex);
    cudaGetSymbolAddress((void**)&sig,    g_sig);
    cudaGetSymbolAddress((void**)&seg,    g_seg);
    cudaGetSymbolAddress((void**)&emb,    g_emb);
    cudaGetSymbolAddress((void**)&ntype,  g_ntype);

    const int EM_SMEM = 75840; // dynamic smem bytes for edge_msg
    cudaFuncSetAttribute(edge_msg, cudaFuncAttributeMaxDynamicSharedMemorySize, EM_SMEM);

    // encoders
    mlp2_646464<<<592, 256>>>(x,     nf0, ne_w1, ne_b1, ne_w2, ne_b2, NN);
    mlp2_646464<<<592, 256>>>(eattr, ef0, ee_w1, ee_b1, ee_w2, ee_b2, NE);

    // MPN steps: nf0 -> nf1 -> nf0 -> out_nf ; ef0 -> ef1 -> ef0 -> out_ef
    const float* nf_in = nf0;  float* nf_out = nf1;
    const float* ef_in = ef0;  float* ef_out = ef1;
    for (int s = 0; s < 3; s++) {
        if (s == 2) { nf_out = out_nf; ef_out = out_ef; }
        cudaMemsetAsync(aggr, 0, (size_t)NN * 64 * sizeof(float));
        node_partials<<<296, 128>>>(nf_in, me_w1, hsrc, htgt, NN);
        edge_msg<<<444, 128, EM_SMEM>>>(ef_in, src, tgt, hsrc, htgt,
                                        me_w1, me_b1, me_w2, me_b2, ef_out, aggr);
        node_update<<<296, 128>>>(nf_in, aggr, nu_w1, nu_b1, nf_out, NN);
        nf_in = nf_out; ef_in = ef_out;
        nf_out = (s == 0) ? nf0 : nf1;
        ef_out = (s == 0) ? ef0 : ef1;
    }

    cudaMemsetAsync(segmax, 0, (size_t)NN * NT * sizeof(unsigned));
    cudaMemsetAsync(segsum, 0, (size_t)NN * NT * sizeof(float));

    node_heads<<<1024, 64>>>(out_nf, nc_w1, nc_b1, nc_w2, nc_b2,
                             cl_w1, cl_b1, cl_w2, cl_b2, ce_w, ce_b,
                             out_node, out_class, ntype, emb, NN);
    edge_head<<<592, 128>>>(out_ef, src, tgt, ec_w1, ec_b1, ec_w2, ec_b2,
                            emb, ntype, sig, ex, seg, segmax);
    softmax_pass2<<<(NE + 255) / 256, 256>>>(seg, segmax, ex, segsum);
    softmax_pass3<<<(NE + 255) / 256, 256>>>(seg, segsum, ex, sig, out_edge);
}